// round 6
// baseline (speedup 1.0000x reference)
#include <cuda_runtime.h>
#include <math.h>

#define Nn 50000
#define Ee 500000
#define Dd 16
#define EFf 8
#define Cc 10
#define Gg 500
#define BN_EPS 1e-5f

// ---------------- device scratch (static, allocation-free) ----------------
__device__ float  g_he[(size_t)Ee * Dd];        // 32 MB  per-edge MLP hidden (tanh)
__device__ float  g_u[(size_t)Nn * Dd * Dd];    // 51 MB  per-node precontraction h@w2
__device__ float  g_v[Nn * Dd];                 // per-node h@b2 term
__device__ float  g_h[Nn * Dd];                 // current node features
__device__ float  g_h2[Nn * Dd];                // pre-BN features
__device__ float  g_agg[Nn * Dd];               // scatter accumulator
__device__ float  g_deg[Nn];                    // in-degree
__device__ double g_stat[2 * Dd];               // BN sum / sumsq
__device__ float  g_mu[Dd], g_rs[Dd];           // BN mean / rsqrt(var+eps)
__device__ int    g_off[Gg + 1];                // segment offsets
__device__ float  g_pooled[Gg * 4 * Dd];        // pooled scratch (fallback path)
__device__ float  g_fcbuf[Gg * Cc];             // fc scratch (fallback path)

// ---------------- kernels ----------------

__global__ void k_init() {
    int i = blockIdx.x * blockDim.x + threadIdx.x;
    if (i < Nn) g_deg[i] = 0.f;
    if (i < 2 * Dd) g_stat[i] = 0.0;
}

__global__ void k_copy_x(const float* __restrict__ x) {
    int i = blockIdx.x * blockDim.x + threadIdx.x;
    if (i < Nn * Dd) g_h[i] = x[i];
}

// per-edge MLP: he = tanh(edge_attr @ w1 + b1); also count in-degree
__global__ void k_edge_mlp(const float* __restrict__ ea,
                           const float* __restrict__ w1,
                           const float* __restrict__ b1,
                           const int*   __restrict__ dst) {
    int t = blockIdx.x * blockDim.x + threadIdx.x;       // Ee*Dd threads
    if (t >= Ee * Dd) return;
    int e = t >> 4, c = t & 15;
    const float* a = ea + (size_t)e * EFf;
    float acc = __ldg(b1 + c);
#pragma unroll
    for (int f = 0; f < EFf; f++)
        acc = fmaf(__ldg(a + f), __ldg(w1 + f * Dd + c), acc);
    g_he[t] = tanhf(acc);
    if (c == 0) atomicAdd(&g_deg[dst[e]], 1.0f);
}

__global__ void k_zero_agg() {
    int i = blockIdx.x * blockDim.x + threadIdx.x;
    if (i < Nn * Dd) g_agg[i] = 0.f;
}

// per-node: u[n,j,o] = sum_i h[n,i]*w2[j,i*16+o];  v[n,o] = sum_i h[n,i]*b2[i*16+o]
__global__ void k_nodepre(const float* __restrict__ w2,
                          const float* __restrict__ b2) {
    __shared__ float sw2[Dd * 272];   // padded rows -> no bank conflict across j-groups
    __shared__ float sh[Dd];
    int j = threadIdx.x >> 4, o = threadIdx.x & 15;
    for (int i = threadIdx.x; i < Dd * Dd * Dd; i += 256) {
        int jj = i >> 8, rest = i & 255;
        sw2[jj * 272 + rest] = w2[i];
    }
    __syncthreads();
    for (int n = blockIdx.x; n < Nn; n += gridDim.x) {
        if (threadIdx.x < Dd) sh[threadIdx.x] = g_h[n * Dd + threadIdx.x];
        __syncthreads();
        float acc = 0.f;
#pragma unroll
        for (int i = 0; i < Dd; i++)
            acc = fmaf(sh[i], sw2[j * 272 + i * Dd + o], acc);
        g_u[(size_t)n * 256 + threadIdx.x] = acc;
        if (j == 0) {
            float vv = 0.f;
#pragma unroll
            for (int i = 0; i < Dd; i++)
                vv = fmaf(sh[i], __ldg(b2 + i * Dd + o), vv);
            g_v[n * Dd + o] = vv;
        }
        __syncthreads();
    }
}

// per-edge: msg[o] = v[s,o] + sum_j he[e,j]*u[s,j,o]; atomic scatter into agg[dst]
__global__ void k_msg(const int* __restrict__ src, const int* __restrict__ dst) {
    int t = blockIdx.x * blockDim.x + threadIdx.x;       // Ee*16 threads exactly
    int e = t >> 4, o = t & 15;
    if (e >= Ee) return;
    int s = src[e], d = dst[e];
    float myhe = g_he[(size_t)e * Dd + o];
    const float* up = g_u + (size_t)s * 256;
    float acc = g_v[s * Dd + o];
#pragma unroll
    for (int j = 0; j < Dd; j++) {
        float hej = __shfl_sync(0xffffffffu, myhe, j, 16);
        acc = fmaf(hej, __ldg(up + j * Dd + o), acc);
    }
    atomicAdd(&g_agg[d * Dd + o], acc);
}

// h2 = agg/deg + h@root + bias; accumulate BN sum/sumsq (block partials -> double atomics)
__global__ void k_update(const float* __restrict__ root,
                         const float* __restrict__ bias) {
    int c = threadIdx.x & 15;
    int local = threadIdx.x >> 4;                        // 16 nodes per block-iter
    float lsum = 0.f, lsq = 0.f;
    float rc[Dd];
#pragma unroll
    for (int i = 0; i < Dd; i++) rc[i] = __ldg(root + i * Dd + c);
    float bc = __ldg(bias + c);
    for (int base = blockIdx.x * 16; base < Nn; base += gridDim.x * 16) {
        int n = base + local;
        if (n < Nn) {
            float acc = g_agg[n * Dd + c] / fmaxf(g_deg[n], 1.0f) + bc;
#pragma unroll
            for (int i = 0; i < Dd; i++)
                acc = fmaf(g_h[n * Dd + i], rc[i], acc);
            g_h2[n * Dd + c] = acc;
            lsum += acc; lsq = fmaf(acc, acc, lsq);
        }
    }
    __shared__ float ssum[256], ssq[256];
    ssum[threadIdx.x] = lsum; ssq[threadIdx.x] = lsq;
    __syncthreads();
    for (int s = 128; s >= 16; s >>= 1) {
        if (threadIdx.x < s) {
            ssum[threadIdx.x] += ssum[threadIdx.x + s];
            ssq[threadIdx.x]  += ssq[threadIdx.x + s];
        }
        __syncthreads();
    }
    if (threadIdx.x < Dd) {
        atomicAdd(&g_stat[threadIdx.x], (double)ssum[threadIdx.x]);
        atomicAdd(&g_stat[Dd + threadIdx.x], (double)ssq[threadIdx.x]);
    }
}

__global__ void k_bnfin() {
    int c = threadIdx.x;
    if (c < Dd) {
        double mu = g_stat[c] / (double)Nn;
        double var = g_stat[Dd + c] / (double)Nn - mu * mu;
        if (var < 0.0) var = 0.0;
        g_mu[c] = (float)mu;
        g_rs[c] = rsqrtf((float)var + BN_EPS);
        g_stat[c] = 0.0; g_stat[Dd + c] = 0.0;           // reset for next layer
    }
}

__global__ void k_apply(const float* __restrict__ gamma,
                        const float* __restrict__ beta,
                        float* __restrict__ hid_out) {
    int i = blockIdx.x * blockDim.x + threadIdx.x;
    if (i >= Nn * Dd) return;
    int c = i & 15;
    float v = (g_h2[i] - g_mu[c]) * g_rs[c] * __ldg(gamma + c) + __ldg(beta + c);
    v = tanhf(v);
    g_h[i] = v;
    if (hid_out) hid_out[i] = v;
}

__global__ void k_offsets(const int* __restrict__ lengths) {
    if (threadIdx.x == 0 && blockIdx.x == 0) {
        int acc = 0;
        for (int g = 0; g < Gg; g++) {
            g_off[g] = (acc < Nn) ? acc : Nn;
            acc += lengths[g];
        }
        g_off[Gg] = (acc < Nn) ? acc : Nn;
    }
}

// segment mean/max/min/sum pooling: one 16-lane group per graph
__global__ void k_pool(float* __restrict__ pooled,
                       const int* __restrict__ lengths) {
    int t = blockIdx.x * blockDim.x + threadIdx.x;
    int g = t >> 4, c = t & 15;
    if (g >= Gg) return;
    int beg = g_off[g], end = g_off[g + 1];
    float s = 0.f, mx = -INFINITY, mn = INFINITY;
    for (int n = beg; n < end; n++) {
        float v = g_h[n * Dd + c];
        s += v; mx = fmaxf(mx, v); mn = fminf(mn, v);
    }
    float cnt = fmaxf((float)lengths[g], 1.0f);
    pooled[g * 64 + c]      = s / cnt;
    pooled[g * 64 + 16 + c] = mx;
    pooled[g * 64 + 32 + c] = mn;
    pooled[g * 64 + 48 + c] = s;
}

// fc1 tanh -> fc2 -> log_softmax; one thread per graph
__global__ void k_head(const float* __restrict__ pooled,
                       const float* __restrict__ fc1w, const float* __restrict__ fc1b,
                       const float* __restrict__ fc2w, const float* __restrict__ fc2b,
                       float* __restrict__ fc_out, float* __restrict__ lsm_out) {
    int g = blockIdx.x * blockDim.x + threadIdx.x;
    if (g >= Gg) return;
    float p[64];
#pragma unroll
    for (int i = 0; i < 64; i++) p[i] = pooled[g * 64 + i];
    float h1[Dd];
#pragma unroll
    for (int c = 0; c < Dd; c++) {
        float acc = __ldg(fc1b + c);
#pragma unroll
        for (int i = 0; i < 64; i++)
            acc = fmaf(p[i], __ldg(fc1w + i * Dd + c), acc);
        h1[c] = tanhf(acc);
    }
    float f[Cc];
    float m = -INFINITY;
#pragma unroll
    for (int c = 0; c < Cc; c++) {
        float acc = __ldg(fc2b + c);
#pragma unroll
        for (int i = 0; i < Dd; i++)
            acc = fmaf(h1[i], __ldg(fc2w + i * Cc + c), acc);
        f[c] = acc;
        fc_out[g * Cc + c] = acc;
        m = fmaxf(m, acc);
    }
    float sum = 0.f;
#pragma unroll
    for (int c = 0; c < Cc; c++) sum += expf(f[c] - m);
    float lse = m + logf(sum);
#pragma unroll
    for (int c = 0; c < Cc; c++) lsm_out[g * Cc + c] = f[c] - lse;
}

// ---------------- launch ----------------
extern "C" void kernel_launch(void* const* d_in, const int* in_sizes, int n_in,
                              void* d_out, int out_size) {
    const float* x         = (const float*)d_in[0];
    const float* edge_attr = (const float*)d_in[1];
    const float* edge_w1   = (const float*)d_in[2];
    const float* edge_b1   = (const float*)d_in[3];
    const float* edge_w2   = (const float*)d_in[4];
    const float* edge_b2   = (const float*)d_in[5];
    const float* root      = (const float*)d_in[6];
    const float* conv_bias = (const float*)d_in[7];
    const float* bn_gamma  = (const float*)d_in[8];
    const float* bn_beta   = (const float*)d_in[9];
    const float* fc1_w     = (const float*)d_in[10];
    const float* fc1_b     = (const float*)d_in[11];
    const float* fc2_w     = (const float*)d_in[12];
    const float* fc2_b     = (const float*)d_in[13];
    const int*   edge_index= (const int*)d_in[14];
    const int*   lengths   = (const int*)d_in[15];
    const int* src = edge_index;
    const int* dst = edge_index + Ee;
    float* out = (float*)d_out;

    // output layout resolution: tuple concat [hidden, pooled, fc, log_softmax]
    const int FULL = Nn * Dd + Gg * 4 * Dd + Gg * Cc + Gg * Cc;  // 842000
    float *hid_dst = nullptr, *pool_dst, *fc_dst, *lsm_dst;
    void *p_pool = nullptr, *p_fc = nullptr;
    cudaGetSymbolAddress(&p_pool, g_pooled);
    cudaGetSymbolAddress(&p_fc, g_fcbuf);
    pool_dst = (float*)p_pool; fc_dst = (float*)p_fc; lsm_dst = (float*)p_fc;
    if (out_size >= FULL) {
        hid_dst  = out;
        pool_dst = out + Nn * Dd;
        fc_dst   = pool_dst + Gg * 4 * Dd;
        lsm_dst  = fc_dst + Gg * Cc;
    } else if (out_size == Gg * Cc) {
        lsm_dst = out;                                   // log_softmax only
    } else if (out_size == 2 * Gg * Cc) {
        fc_dst = out; lsm_dst = out + Gg * Cc;           // fc + log_softmax
    } else if (out_size == Nn * Dd) {
        hid_dst = out;                                   // hidden only
    }

    const int B = 256;
    k_init<<<(Nn + B - 1) / B, B>>>();
    k_copy_x<<<(Nn * Dd + B - 1) / B, B>>>(x);
    k_edge_mlp<<<(Ee * Dd) / B, B>>>(edge_attr, edge_w1, edge_b1, dst);

    for (int l = 0; l < 3; l++) {
        k_zero_agg<<<(Nn * Dd + B - 1) / B, B>>>();
        k_nodepre<<<1024, B>>>(edge_w2, edge_b2);
        k_msg<<<(Ee * Dd) / B, B>>>(src, dst);
        k_update<<<512, B>>>(root + l * Dd * Dd, conv_bias + l * Dd);
        k_bnfin<<<1, 32>>>();
        k_apply<<<(Nn * Dd + B - 1) / B, B>>>(bn_gamma + l * Dd, bn_beta + l * Dd,
                                              (l == 2) ? hid_dst : nullptr);
    }

    k_offsets<<<1, 32>>>(lengths);
    k_pool<<<(Gg * Dd + B - 1) / B, B>>>(pool_dst, lengths);
    k_head<<<(Gg + 127) / 128, 128>>>(pool_dst, fc1_w, fc1_b, fc2_w, fc2_b,
                                      fc_dst, lsm_dst);
}

// round 8
// speedup vs baseline: 1.0247x; 1.0247x over previous
#include <cuda_runtime.h>
#include <math.h>

#define Nn 50000
#define Ee 500000
#define Dd 16
#define EFf 8
#define Cc 10
#define Gg 500
#define BN_EPS 1e-5f

// ---------------- device scratch (static, allocation-free) ----------------
__device__ float  g_he[(size_t)Ee * Dd];        // 32 MB  per-edge MLP hidden (tanh)
__device__ float  g_u[(size_t)Nn * Dd * Dd];    // 51 MB  per-node precontraction h@w2
__device__ float  g_v[Nn * Dd];                 // per-node h@b2 term
__device__ float  g_h[Nn * Dd];                 // current node features
__device__ float  g_h2[Nn * Dd];                // pre-BN features
__device__ float  g_agg[Nn * Dd];               // scatter accumulator
__device__ float  g_deg[Nn];                    // in-degree
__device__ double g_stat[2 * Dd];               // BN sum / sumsq
__device__ float  g_mu[Dd], g_rs[Dd];           // BN mean / rsqrt(var+eps)
__device__ int    g_off[Gg + 1];                // segment offsets
__device__ float  g_pooled[Gg * 4 * Dd];        // pooled scratch (fallback path)
__device__ float  g_fcbuf[Gg * Cc];             // fc scratch (fallback path)

// ---------------- kernels ----------------

__global__ void k_init() {
    int i = blockIdx.x * blockDim.x + threadIdx.x;
    if (i < Nn) g_deg[i] = 0.f;
    if (i < 2 * Dd) g_stat[i] = 0.0;
}

__global__ void k_copy_x(const float* __restrict__ x) {
    int i = blockIdx.x * blockDim.x + threadIdx.x;
    if (i < Nn * Dd) g_h[i] = x[i];
}

// per-edge MLP: he = tanh(edge_attr @ w1 + b1); also count in-degree
__global__ void k_edge_mlp(const float* __restrict__ ea,
                           const float* __restrict__ w1,
                           const float* __restrict__ b1,
                           const int*   __restrict__ dst) {
    int t = blockIdx.x * blockDim.x + threadIdx.x;       // Ee*Dd threads
    if (t >= Ee * Dd) return;
    int e = t >> 4, c = t & 15;
    const float* a = ea + (size_t)e * EFf;
    float acc = __ldg(b1 + c);
#pragma unroll
    for (int f = 0; f < EFf; f++)
        acc = fmaf(__ldg(a + f), __ldg(w1 + f * Dd + c), acc);
    g_he[t] = tanhf(acc);
    if (c == 0) atomicAdd(&g_deg[dst[e]], 1.0f);
}

__global__ void k_zero_agg() {
    int i = blockIdx.x * blockDim.x + threadIdx.x;
    if (i < Nn * Dd) g_agg[i] = 0.f;
}

// per-node: u[n,j,o] = sum_i h[n,i]*w2[j,i*16+o];  v[n,o] = sum_i h[n,i]*b2[i*16+o]
__global__ void k_nodepre(const float* __restrict__ w2,
                          const float* __restrict__ b2) {
    __shared__ float sw2[Dd * 272];   // padded rows -> no bank conflict across j-groups
    __shared__ float sh[Dd];
    int j = threadIdx.x >> 4, o = threadIdx.x & 15;
    for (int i = threadIdx.x; i < Dd * Dd * Dd; i += 256) {
        int jj = i >> 8, rest = i & 255;
        sw2[jj * 272 + rest] = w2[i];
    }
    __syncthreads();
    for (int n = blockIdx.x; n < Nn; n += gridDim.x) {
        if (threadIdx.x < Dd) sh[threadIdx.x] = g_h[n * Dd + threadIdx.x];
        __syncthreads();
        float acc = 0.f;
#pragma unroll
        for (int i = 0; i < Dd; i++)
            acc = fmaf(sh[i], sw2[j * 272 + i * Dd + o], acc);
        g_u[(size_t)n * 256 + threadIdx.x] = acc;
        if (j == 0) {
            float vv = 0.f;
#pragma unroll
            for (int i = 0; i < Dd; i++)
                vv = fmaf(sh[i], __ldg(b2 + i * Dd + o), vv);
            g_v[n * Dd + o] = vv;
        }
        __syncthreads();
    }
}

// per-edge: msg[o] = v[s,o] + sum_j he[e,j]*u[s,j,o]; atomic scatter into agg[dst]
__global__ void k_msg(const int* __restrict__ src, const int* __restrict__ dst) {
    int t = blockIdx.x * blockDim.x + threadIdx.x;       // Ee*16 threads exactly
    int e = t >> 4, o = t & 15;
    if (e >= Ee) return;
    int s = src[e], d = dst[e];
    float myhe = g_he[(size_t)e * Dd + o];
    const float* up = g_u + (size_t)s * 256;
    float acc = g_v[s * Dd + o];
#pragma unroll
    for (int j = 0; j < Dd; j++) {
        float hej = __shfl_sync(0xffffffffu, myhe, j, 16);
        acc = fmaf(hej, __ldg(up + j * Dd + o), acc);
    }
    atomicAdd(&g_agg[d * Dd + o], acc);
}

// h2 = agg/deg + h@root + bias; accumulate BN sum/sumsq (block partials -> double atomics)
__global__ void k_update(const float* __restrict__ root,
                         const float* __restrict__ bias) {
    int c = threadIdx.x & 15;
    int local = threadIdx.x >> 4;                        // 16 nodes per block-iter
    float lsum = 0.f, lsq = 0.f;
    float rc[Dd];
#pragma unroll
    for (int i = 0; i < Dd; i++) rc[i] = __ldg(root + i * Dd + c);
    float bc = __ldg(bias + c);
    for (int base = blockIdx.x * 16; base < Nn; base += gridDim.x * 16) {
        int n = base + local;
        if (n < Nn) {
            float acc = g_agg[n * Dd + c] / fmaxf(g_deg[n], 1.0f) + bc;
#pragma unroll
            for (int i = 0; i < Dd; i++)
                acc = fmaf(g_h[n * Dd + i], rc[i], acc);
            g_h2[n * Dd + c] = acc;
            lsum += acc; lsq = fmaf(acc, acc, lsq);
        }
    }
    __shared__ float ssum[256], ssq[256];
    ssum[threadIdx.x] = lsum; ssq[threadIdx.x] = lsq;
    __syncthreads();
    for (int s = 128; s >= 16; s >>= 1) {
        if (threadIdx.x < s) {
            ssum[threadIdx.x] += ssum[threadIdx.x + s];
            ssq[threadIdx.x]  += ssq[threadIdx.x + s];
        }
        __syncthreads();
    }
    if (threadIdx.x < Dd) {
        atomicAdd(&g_stat[threadIdx.x], (double)ssum[threadIdx.x]);
        atomicAdd(&g_stat[Dd + threadIdx.x], (double)ssq[threadIdx.x]);
    }
}

__global__ void k_bnfin() {
    int c = threadIdx.x;
    if (c < Dd) {
        double mu = g_stat[c] / (double)Nn;
        double var = g_stat[Dd + c] / (double)Nn - mu * mu;
        if (var < 0.0) var = 0.0;
        g_mu[c] = (float)mu;
        g_rs[c] = rsqrtf((float)var + BN_EPS);
        g_stat[c] = 0.0; g_stat[Dd + c] = 0.0;           // reset for next layer
    }
}

__global__ void k_apply(const float* __restrict__ gamma,
                        const float* __restrict__ beta,
                        float* __restrict__ hid_out) {
    int i = blockIdx.x * blockDim.x + threadIdx.x;
    if (i >= Nn * Dd) return;
    int c = i & 15;
    float v = (g_h2[i] - g_mu[c]) * g_rs[c] * __ldg(gamma + c) + __ldg(beta + c);
    v = tanhf(v);
    g_h[i] = v;
    if (hid_out) hid_out[i] = v;
}

__global__ void k_offsets(const int* __restrict__ lengths) {
    if (threadIdx.x == 0 && blockIdx.x == 0) {
        int acc = 0;
        for (int g = 0; g < Gg; g++) {
            g_off[g] = (acc < Nn) ? acc : Nn;
            acc += lengths[g];
        }
        g_off[Gg] = (acc < Nn) ? acc : Nn;
    }
}

// segment mean/max/min/sum pooling: one 16-lane group per graph
__global__ void k_pool(float* __restrict__ pooled,
                       const int* __restrict__ lengths) {
    int t = blockIdx.x * blockDim.x + threadIdx.x;
    int g = t >> 4, c = t & 15;
    if (g >= Gg) return;
    int beg = g_off[g], end = g_off[g + 1];
    float s = 0.f, mx = -INFINITY, mn = INFINITY;
    for (int n = beg; n < end; n++) {
        float v = g_h[n * Dd + c];
        s += v; mx = fmaxf(mx, v); mn = fminf(mn, v);
    }
    float cnt = fmaxf((float)lengths[g], 1.0f);
    pooled[g * 64 + c]      = s / cnt;
    pooled[g * 64 + 16 + c] = mx;
    pooled[g * 64 + 32 + c] = mn;
    pooled[g * 64 + 48 + c] = s;
}

// fc1 tanh -> fc2 -> log_softmax; one thread per graph
__global__ void k_head(const float* __restrict__ pooled,
                       const float* __restrict__ fc1w, const float* __restrict__ fc1b,
                       const float* __restrict__ fc2w, const float* __restrict__ fc2b,
                       float* __restrict__ fc_out, float* __restrict__ lsm_out) {
    int g = blockIdx.x * blockDim.x + threadIdx.x;
    if (g >= Gg) return;
    float p[64];
#pragma unroll
    for (int i = 0; i < 64; i++) p[i] = pooled[g * 64 + i];
    float h1[Dd];
#pragma unroll
    for (int c = 0; c < Dd; c++) {
        float acc = __ldg(fc1b + c);
#pragma unroll
        for (int i = 0; i < 64; i++)
            acc = fmaf(p[i], __ldg(fc1w + i * Dd + c), acc);
        h1[c] = tanhf(acc);
    }
    float f[Cc];
    float m = -INFINITY;
#pragma unroll
    for (int c = 0; c < Cc; c++) {
        float acc = __ldg(fc2b + c);
#pragma unroll
        for (int i = 0; i < Dd; i++)
            acc = fmaf(h1[i], __ldg(fc2w + i * Cc + c), acc);
        f[c] = acc;
        fc_out[g * Cc + c] = acc;
        m = fmaxf(m, acc);
    }
    float sum = 0.f;
#pragma unroll
    for (int c = 0; c < Cc; c++) sum += expf(f[c] - m);
    float lse = m + logf(sum);
#pragma unroll
    for (int c = 0; c < Cc; c++) lsm_out[g * Cc + c] = f[c] - lse;
}

// ---------------- launch ----------------
extern "C" void kernel_launch(void* const* d_in, const int* in_sizes, int n_in,
                              void* d_out, int out_size) {
    const float* x         = (const float*)d_in[0];
    const float* edge_attr = (const float*)d_in[1];
    const float* edge_w1   = (const float*)d_in[2];
    const float* edge_b1   = (const float*)d_in[3];
    const float* edge_w2   = (const float*)d_in[4];
    const float* edge_b2   = (const float*)d_in[5];
    const float* root      = (const float*)d_in[6];
    const float* conv_bias = (const float*)d_in[7];
    const float* bn_gamma  = (const float*)d_in[8];
    const float* bn_beta   = (const float*)d_in[9];
    const float* fc1_w     = (const float*)d_in[10];
    const float* fc1_b     = (const float*)d_in[11];
    const float* fc2_w     = (const float*)d_in[12];
    const float* fc2_b     = (const float*)d_in[13];
    const int*   edge_index= (const int*)d_in[14];
    const int*   lengths   = (const int*)d_in[15];
    const int* src = edge_index;
    const int* dst = edge_index + Ee;
    float* out = (float*)d_out;

    // output layout resolution: tuple concat [hidden, pooled, fc, log_softmax]
    const int FULL = Nn * Dd + Gg * 4 * Dd + Gg * Cc + Gg * Cc;  // 842000
    float *hid_dst = nullptr, *pool_dst, *fc_dst, *lsm_dst;
    void *p_pool = nullptr, *p_fc = nullptr;
    cudaGetSymbolAddress(&p_pool, g_pooled);
    cudaGetSymbolAddress(&p_fc, g_fcbuf);
    pool_dst = (float*)p_pool; fc_dst = (float*)p_fc; lsm_dst = (float*)p_fc;
    if (out_size >= FULL) {
        hid_dst  = out;
        pool_dst = out + Nn * Dd;
        fc_dst   = pool_dst + Gg * 4 * Dd;
        lsm_dst  = fc_dst + Gg * Cc;
    } else if (out_size == Gg * Cc) {
        lsm_dst = out;                                   // log_softmax only
    } else if (out_size == 2 * Gg * Cc) {
        fc_dst = out; lsm_dst = out + Gg * Cc;           // fc + log_softmax
    } else if (out_size == Nn * Dd) {
        hid_dst = out;                                   // hidden only
    }

    const int B = 256;
    k_init<<<(Nn + B - 1) / B, B>>>();
    k_copy_x<<<(Nn * Dd + B - 1) / B, B>>>(x);
    k_edge_mlp<<<(Ee * Dd) / B, B>>>(edge_attr, edge_w1, edge_b1, dst);

    for (int l = 0; l < 3; l++) {
        k_zero_agg<<<(Nn * Dd + B - 1) / B, B>>>();
        k_nodepre<<<1024, B>>>(edge_w2, edge_b2);
        k_msg<<<(Ee * Dd) / B, B>>>(src, dst);
        k_update<<<512, B>>>(root + l * Dd * Dd, conv_bias + l * Dd);
        k_bnfin<<<1, 32>>>();
        k_apply<<<(Nn * Dd + B - 1) / B, B>>>(bn_gamma + l * Dd, bn_beta + l * Dd,
                                              (l == 2) ? hid_dst : nullptr);
    }

    k_offsets<<<1, 32>>>(lengths);
    k_pool<<<(Gg * Dd + B - 1) / B, B>>>(pool_dst, lengths);
    k_head<<<(Gg + 127) / 128, 128>>>(pool_dst, fc1_w, fc1_b, fc2_w, fc2_b,
                                      fc_dst, lsm_dst);
}

// round 11
// speedup vs baseline: 1.2517x; 1.2215x over previous
#include <cuda_runtime.h>
#include <math.h>

#define Nn 50000
#define Ee 500000
#define Dd 16
#define EFf 8
#define Cc 10
#define Gg 500
#define BN_EPS 1e-5f
#define NBS 196   // ceil(Nn/256)

// ---------------- device scratch (static, allocation-free) ----------------
__device__ float  g_he[(size_t)Ee * Dd];     // per-edge MLP hidden, PERMUTED to dst-sorted order
__device__ float  g_h[Nn * Dd];              // current node features
__device__ float  g_h2[Nn * Dd];             // pre-BN features
__device__ int    g_cnt[Nn];                 // histogram / scatter cursor
__device__ int    g_eoff[Nn + 1];            // CSR offsets (edges sorted by dst)
__device__ int    g_bsum[256];               // scan block sums
__device__ int    g_srcs[Ee];                // src id, dst-sorted order
__device__ int    g_eid[Ee];                 // original edge id, dst-sorted order
__device__ double g_stat[2 * Dd];            // BN sum / sumsq
__device__ float  g_mu[Dd], g_rs[Dd];        // BN mean / rsqrt(var+eps)
__device__ int    g_off[Gg + 1];             // graph segment offsets
__device__ float  g_pooled[Gg * 4 * Dd];     // pooled scratch (fallback path)
__device__ float  g_fcbuf[Gg * Cc];          // fc scratch (fallback path)

// ---------------- setup kernels ----------------

__global__ void k_init() {
    int i = blockIdx.x * blockDim.x + threadIdx.x;
    if (i < Nn) g_cnt[i] = 0;
    if (i < 2 * Dd) g_stat[i] = 0.0;
}

__global__ void k_copy_x(const float* __restrict__ x) {
    int i = blockIdx.x * blockDim.x + threadIdx.x;
    if (i < Nn * Dd) g_h[i] = x[i];
}

__global__ void k_hist(const int* __restrict__ dst) {
    int e = blockIdx.x * blockDim.x + threadIdx.x;
    if (e < Ee) atomicAdd(&g_cnt[dst[e]], 1);
}

__global__ void k_scanA() {
    __shared__ int sh[256];
    int t = threadIdx.x;
    int i = blockIdx.x * 256 + t;
    int v = (i < Nn) ? g_cnt[i] : 0;
    sh[t] = v; __syncthreads();
    for (int ofs = 1; ofs < 256; ofs <<= 1) {
        int add = (t >= ofs) ? sh[t - ofs] : 0;
        __syncthreads();
        sh[t] += add;
        __syncthreads();
    }
    if (i < Nn) g_eoff[i] = sh[t] - v;         // exclusive
    if (t == 255) g_bsum[blockIdx.x] = sh[255];
}

__global__ void k_scanB() {
    __shared__ int sh[256];
    int t = threadIdx.x;
    int v = (t < NBS) ? g_bsum[t] : 0;
    sh[t] = v; __syncthreads();
    for (int ofs = 1; ofs < 256; ofs <<= 1) {
        int add = (t >= ofs) ? sh[t - ofs] : 0;
        __syncthreads();
        sh[t] += add;
        __syncthreads();
    }
    if (t < NBS) g_bsum[t] = sh[t] - v;        // exclusive
}

__global__ void k_scanC() {
    int i = blockIdx.x * blockDim.x + threadIdx.x;
    if (i < Nn) { g_eoff[i] += g_bsum[i >> 8]; g_cnt[i] = 0; }
    if (i == 0) g_eoff[Nn] = Ee;
}

__global__ void k_scatter(const int* __restrict__ src, const int* __restrict__ dst) {
    int e = blockIdx.x * blockDim.x + threadIdx.x;
    if (e >= Ee) return;
    int d = dst[e];
    int r = atomicAdd(&g_cnt[d], 1);
    int pos = g_eoff[d] + r;
    g_srcs[pos] = src[e];
    g_eid[pos] = e;
}

// per-edge MLP computed into SORTED position: he[p] = tanh(edge_attr[eid[p]] @ w1 + b1)
__global__ void k_edge_mlp(const float* __restrict__ ea,
                           const float* __restrict__ w1,
                           const float* __restrict__ b1) {
    int t = blockIdx.x * blockDim.x + threadIdx.x;       // Ee*Dd threads
    if (t >= Ee * Dd) return;
    int p = t >> 4, c = t & 15;
    int e = g_eid[p];
    const float* a = ea + (size_t)e * EFf;
    float acc = __ldg(b1 + c);
#pragma unroll
    for (int f = 0; f < EFf; f++)
        acc = fmaf(__ldg(a + f), __ldg(w1 + f * Dd + c), acc);
    g_he[t] = tanhf(acc);
}

// ---------------- fused NNConv layer ----------------
// One warp per dst node: accumulate S[j,i] = sum_e he[e,j]*h[src,i] and
// T[i] = sum_e h[src,i] in registers, then contract with w2/b2 from shared,
// add deg-mean + root term + bias, write h2, accumulate BN stats.
__global__ void k_conv(const float* __restrict__ w2, const float* __restrict__ b2,
                       const float* __restrict__ root, const float* __restrict__ bias) {
    __shared__ float sw2[4096];          // w2[j*256 + i*16 + o]
    __shared__ float sb2[256];           // b2[i*16 + o]
    __shared__ float sroot[256];         // root[i*16 + o]
    __shared__ float sbias[16];
    __shared__ float sS[8][272];         // per-warp staging: 256 S + 16 T
    __shared__ float bsum[16], bsq[16];

    for (int i = threadIdx.x; i < 4096; i += 256) sw2[i] = w2[i];
    for (int i = threadIdx.x; i < 256; i += 256) { sb2[i] = b2[i]; sroot[i] = root[i]; }
    if (threadIdx.x < 16) { sbias[threadIdx.x] = bias[threadIdx.x];
                            bsum[threadIdx.x] = 0.f; bsq[threadIdx.x] = 0.f; }
    __syncthreads();

    const unsigned FULL = 0xffffffffu;
    int warp = threadIdx.x >> 5, lane = threadIdx.x & 31;
    int j = lane >> 1;                   // 0..15
    int ibase = (lane & 1) * 8;          // this lane's i-range for S
    int o = lane & 15;                   // epilogue output channel
    int hf = lane >> 4;                  // epilogue i-half
    float* ss = sS[warp];
    float lsum = 0.f, lsq = 0.f;         // BN partials on lanes 0..15 (channel o)

    for (int d = blockIdx.x * 8 + warp; d < Nn; d += gridDim.x * 8) {
        int beg = g_eoff[d], end = g_eoff[d + 1];
        float S0=0.f,S1=0.f,S2=0.f,S3=0.f,S4=0.f,S5=0.f,S6=0.f,S7=0.f;
        float T = 0.f;
        for (int p = beg; p < end; p++) {
            int s = g_srcs[p];
            float a = (lane < 16) ? g_he[(size_t)p * 16 + lane]
                                  : g_h[s * 16 + (lane - 16)];
            float hej = __shfl_sync(FULL, a, j);
            T += __shfl_sync(FULL, a, 16 + (lane & 15));
            S0 = fmaf(hej, __shfl_sync(FULL, a, 16 + ibase + 0), S0);
            S1 = fmaf(hej, __shfl_sync(FULL, a, 16 + ibase + 1), S1);
            S2 = fmaf(hej, __shfl_sync(FULL, a, 16 + ibase + 2), S2);
            S3 = fmaf(hej, __shfl_sync(FULL, a, 16 + ibase + 3), S3);
            S4 = fmaf(hej, __shfl_sync(FULL, a, 16 + ibase + 4), S4);
            S5 = fmaf(hej, __shfl_sync(FULL, a, 16 + ibase + 5), S5);
            S6 = fmaf(hej, __shfl_sync(FULL, a, 16 + ibase + 6), S6);
            S7 = fmaf(hej, __shfl_sync(FULL, a, 16 + ibase + 7), S7);
        }
        // stage S,T to shared for the contraction
        int sb = j * 16 + ibase;
        ss[sb+0]=S0; ss[sb+1]=S1; ss[sb+2]=S2; ss[sb+3]=S3;
        ss[sb+4]=S4; ss[sb+5]=S5; ss[sb+6]=S6; ss[sb+7]=S7;
        if (lane < 16) ss[256 + lane] = T;
        __syncwarp();

        // agg[o] = sum_{j,i} w2[j,i,o]*S[j,i] + sum_i b2[i,o]*T[i]
        // lanes 0..15 handle i in [0,8), lanes 16..31 handle i in [8,16)
        float acc = 0.f;
#pragma unroll
        for (int jj = 0; jj < 16; jj++) {
            const float4 s0 = *(const float4*)&ss[jj * 16 + hf * 8];
            const float4 s1 = *(const float4*)&ss[jj * 16 + hf * 8 + 4];
            const float* w = &sw2[(jj * 16 + hf * 8) * 16 + o];
            acc = fmaf(s0.x, w[0],   acc);
            acc = fmaf(s0.y, w[16],  acc);
            acc = fmaf(s0.z, w[32],  acc);
            acc = fmaf(s0.w, w[48],  acc);
            acc = fmaf(s1.x, w[64],  acc);
            acc = fmaf(s1.y, w[80],  acc);
            acc = fmaf(s1.z, w[96],  acc);
            acc = fmaf(s1.w, w[112], acc);
        }
        {
            const float4 t0 = *(const float4*)&ss[256 + hf * 8];
            const float4 t1 = *(const float4*)&ss[256 + hf * 8 + 4];
            const float* b = &sb2[hf * 8 * 16 + o];
            acc = fmaf(t0.x, b[0],   acc);
            acc = fmaf(t0.y, b[16],  acc);
            acc = fmaf(t0.z, b[32],  acc);
            acc = fmaf(t0.w, b[48],  acc);
            acc = fmaf(t1.x, b[64],  acc);
            acc = fmaf(t1.y, b[80],  acc);
            acc = fmaf(t1.z, b[96],  acc);
            acc = fmaf(t1.w, b[112], acc);
        }
        acc += __shfl_down_sync(FULL, acc, 16);   // combine i-halves -> lanes 0..15

        // root term + bias + deg-mean
        float hd = (lane < 16) ? g_h[(size_t)d * 16 + lane] : 0.f;
        float rt = 0.f;
#pragma unroll
        for (int i = 0; i < 16; i++) {
            float hdi = __shfl_sync(FULL, hd, i);
            rt = fmaf(hdi, sroot[i * 16 + o], rt);
        }
        if (lane < 16) {
            float degf = fmaxf((float)(end - beg), 1.0f);
            float res = acc / degf + rt + sbias[o];
            g_h2[(size_t)d * 16 + o] = res;
            lsum += res;
            lsq = fmaf(res, res, lsq);
        }
        __syncwarp();   // protect ss before next node's staging
    }

    // BN block reduction -> global double atomics
    if (lane < 16) {
        atomicAdd(&bsum[o], lsum);
        atomicAdd(&bsq[o], lsq);
    }
    __syncthreads();
    if (threadIdx.x < 16) {
        atomicAdd(&g_stat[threadIdx.x], (double)bsum[threadIdx.x]);
        atomicAdd(&g_stat[Dd + threadIdx.x], (double)bsq[threadIdx.x]);
    }
}

__global__ void k_bnfin() {
    int c = threadIdx.x;
    if (c < Dd) {
        double mu = g_stat[c] / (double)Nn;
        double var = g_stat[Dd + c] / (double)Nn - mu * mu;
        if (var < 0.0) var = 0.0;
        g_mu[c] = (float)mu;
        g_rs[c] = rsqrtf((float)var + BN_EPS);
        g_stat[c] = 0.0; g_stat[Dd + c] = 0.0;    // reset for next layer
    }
}

__global__ void k_apply(const float* __restrict__ gamma,
                        const float* __restrict__ beta,
                        float* __restrict__ hid_out) {
    int i = blockIdx.x * blockDim.x + threadIdx.x;
    if (i >= Nn * Dd) return;
    int c = i & 15;
    float v = (g_h2[i] - g_mu[c]) * g_rs[c] * __ldg(gamma + c) + __ldg(beta + c);
    v = tanhf(v);
    g_h[i] = v;
    if (hid_out) hid_out[i] = v;
}

// ---------------- readout ----------------

__global__ void k_offsets(const int* __restrict__ lengths) {
    if (threadIdx.x == 0 && blockIdx.x == 0) {
        int acc = 0;
        for (int g = 0; g < Gg; g++) {
            g_off[g] = (acc < Nn) ? acc : Nn;
            acc += lengths[g];
        }
        g_off[Gg] = (acc < Nn) ? acc : Nn;
    }
}

__global__ void k_pool(float* __restrict__ pooled,
                       const int* __restrict__ lengths) {
    int t = blockIdx.x * blockDim.x + threadIdx.x;
    int g = t >> 4, c = t & 15;
    if (g >= Gg) return;
    int beg = g_off[g], end = g_off[g + 1];
    float s = 0.f, mx = -INFINITY, mn = INFINITY;
    for (int n = beg; n < end; n++) {
        float v = g_h[n * Dd + c];
        s += v; mx = fmaxf(mx, v); mn = fminf(mn, v);
    }
    float cnt = fmaxf((float)lengths[g], 1.0f);
    pooled[g * 64 + c]      = s / cnt;
    pooled[g * 64 + 16 + c] = mx;
    pooled[g * 64 + 32 + c] = mn;
    pooled[g * 64 + 48 + c] = s;
}

__global__ void k_head(const float* __restrict__ pooled,
                       const float* __restrict__ fc1w, const float* __restrict__ fc1b,
                       const float* __restrict__ fc2w, const float* __restrict__ fc2b,
                       float* __restrict__ fc_out, float* __restrict__ lsm_out) {
    int g = blockIdx.x * blockDim.x + threadIdx.x;
    if (g >= Gg) return;
    float p[64];
#pragma unroll
    for (int i = 0; i < 64; i++) p[i] = pooled[g * 64 + i];
    float h1[Dd];
#pragma unroll
    for (int c = 0; c < Dd; c++) {
        float acc = __ldg(fc1b + c);
#pragma unroll
        for (int i = 0; i < 64; i++)
            acc = fmaf(p[i], __ldg(fc1w + i * Dd + c), acc);
        h1[c] = tanhf(acc);
    }
    float f[Cc];
    float m = -INFINITY;
#pragma unroll
    for (int c = 0; c < Cc; c++) {
        float acc = __ldg(fc2b + c);
#pragma unroll
        for (int i = 0; i < Dd; i++)
            acc = fmaf(h1[i], __ldg(fc2w + i * Cc + c), acc);
        f[c] = acc;
        fc_out[g * Cc + c] = acc;
        m = fmaxf(m, acc);
    }
    float sum = 0.f;
#pragma unroll
    for (int c = 0; c < Cc; c++) sum += expf(f[c] - m);
    float lse = m + logf(sum);
#pragma unroll
    for (int c = 0; c < Cc; c++) lsm_out[g * Cc + c] = f[c] - lse;
}

// ---------------- launch ----------------
extern "C" void kernel_launch(void* const* d_in, const int* in_sizes, int n_in,
                              void* d_out, int out_size) {
    const float* x         = (const float*)d_in[0];
    const float* edge_attr = (const float*)d_in[1];
    const float* edge_w1   = (const float*)d_in[2];
    const float* edge_b1   = (const float*)d_in[3];
    const float* edge_w2   = (const float*)d_in[4];
    const float* edge_b2   = (const float*)d_in[5];
    const float* root      = (const float*)d_in[6];
    const float* conv_bias = (const float*)d_in[7];
    const float* bn_gamma  = (const float*)d_in[8];
    const float* bn_beta   = (const float*)d_in[9];
    const float* fc1_w     = (const float*)d_in[10];
    const float* fc1_b     = (const float*)d_in[11];
    const float* fc2_w     = (const float*)d_in[12];
    const float* fc2_b     = (const float*)d_in[13];
    const int*   edge_index= (const int*)d_in[14];
    const int*   lengths   = (const int*)d_in[15];
    const int* src = edge_index;
    const int* dst = edge_index + Ee;
    float* out = (float*)d_out;

    // output layout resolution: tuple concat [hidden, pooled, fc, log_softmax]
    const int FULL = Nn * Dd + Gg * 4 * Dd + Gg * Cc + Gg * Cc;  // 842000
    float *hid_dst = nullptr, *pool_dst, *fc_dst, *lsm_dst;
    void *p_pool = nullptr, *p_fc = nullptr;
    cudaGetSymbolAddress(&p_pool, g_pooled);
    cudaGetSymbolAddress(&p_fc, g_fcbuf);
    pool_dst = (float*)p_pool; fc_dst = (float*)p_fc; lsm_dst = (float*)p_fc;
    if (out_size >= FULL) {
        hid_dst  = out;
        pool_dst = out + Nn * Dd;
        fc_dst   = pool_dst + Gg * 4 * Dd;
        lsm_dst  = fc_dst + Gg * Cc;
    } else if (out_size == Gg * Cc) {
        lsm_dst = out;
    } else if (out_size == 2 * Gg * Cc) {
        fc_dst = out; lsm_dst = out + Gg * Cc;
    } else if (out_size == Nn * Dd) {
        hid_dst = out;
    }

    const int B = 256;
    k_init<<<(Nn + B - 1) / B, B>>>();
    k_copy_x<<<(Nn * Dd + B - 1) / B, B>>>(x);
    k_hist<<<(Ee + B - 1) / B, B>>>(dst);
    k_scanA<<<NBS, 256>>>();
    k_scanB<<<1, 256>>>();
    k_scanC<<<(Nn + B - 1) / B, B>>>();
    k_scatter<<<(Ee + B - 1) / B, B>>>(src, dst);
    k_edge_mlp<<<(Ee * Dd) / B, B>>>(edge_attr, edge_w1, edge_b1);

    for (int l = 0; l < 3; l++) {
        k_conv<<<1184, 256>>>(edge_w2, edge_b2, root + l * Dd * Dd, conv_bias + l * Dd);
        k_bnfin<<<1, 32>>>();
        k_apply<<<(Nn * Dd + B - 1) / B, B>>>(bn_gamma + l * Dd, bn_beta + l * Dd,
                                              (l == 2) ? hid_dst : nullptr);
    }

    k_offsets<<<1, 32>>>(lengths);
    k_pool<<<(Gg * Dd + B - 1) / B, B>>>(pool_dst, lengths);
    k_head<<<(Gg + 127) / 128, 128>>>(pool_dst, fc1_w, fc1_b, fc2_w, fc2_b,
                                      fc_dst, lsm_dst);
}

// round 14
// speedup vs baseline: 1.3527x; 1.0807x over previous
#include <cuda_runtime.h>
#include <math.h>

#define Nn 50000
#define Ee 500000
#define Dd 16
#define EFf 8
#define Cc 10
#define Gg 500
#define BN_EPS 1e-5f
#define NBS 196   // ceil(Nn/256)

// ---------------- device scratch (static, allocation-free) ----------------
__device__ float  g_he[(size_t)Ee * Dd];     // per-edge MLP hidden, dst-sorted order
__device__ float  g_h[Nn * Dd];              // current node features
__device__ float  g_h2[Nn * Dd];             // pre-BN features
__device__ int    g_cnt[Nn];                 // histogram
__device__ int    g_rank[Ee];                // per-edge rank within its dst bucket
__device__ int    g_eoff[Nn + 1];            // CSR offsets (edges sorted by dst)
__device__ int    g_bsum[256];               // scan block sums
__device__ int    g_srcs[Ee];                // src id, dst-sorted order
__device__ double g_stat3[3 * 32];           // per-layer BN sum/sumsq slots
__device__ float  g_pooled[Gg * 4 * Dd];     // pooled scratch (fallback path)
__device__ float  g_fcbuf[Gg * Cc];          // fc scratch (fallback path)

// fast tanh: 1 - 2/(e^{2x}+1); exact at +/-inf, ~1e-6 rel err
__device__ __forceinline__ float ftanh(float x) {
    float e = __expf(2.0f * x);
    return 1.0f - __fdividef(2.0f, e + 1.0f);
}

// ---------------- setup kernels ----------------

__global__ void k_setup(const float* __restrict__ x) {
    int i = blockIdx.x * blockDim.x + threadIdx.x;
    if (i < Nn * Dd) g_h[i] = x[i];
    if (i < Nn) g_cnt[i] = 0;
    if (i < 3 * 32) g_stat3[i] = 0.0;
}

__global__ void k_hist(const int* __restrict__ dst) {
    int e = blockIdx.x * blockDim.x + threadIdx.x;
    if (e < Ee) g_rank[e] = atomicAdd(&g_cnt[dst[e]], 1);
}

__global__ void k_scanA() {
    __shared__ int sh[256];
    int t = threadIdx.x;
    int i = blockIdx.x * 256 + t;
    int v = (i < Nn) ? g_cnt[i] : 0;
    sh[t] = v; __syncthreads();
    for (int ofs = 1; ofs < 256; ofs <<= 1) {
        int add = (t >= ofs) ? sh[t - ofs] : 0;
        __syncthreads();
        sh[t] += add;
        __syncthreads();
    }
    if (i < Nn) g_eoff[i] = sh[t] - v;         // exclusive
    if (t == 255) g_bsum[blockIdx.x] = sh[255];
}

__global__ void k_scanB() {
    __shared__ int sh[256];
    int t = threadIdx.x;
    int v = (t < NBS) ? g_bsum[t] : 0;
    sh[t] = v; __syncthreads();
    for (int ofs = 1; ofs < 256; ofs <<= 1) {
        int add = (t >= ofs) ? sh[t - ofs] : 0;
        __syncthreads();
        sh[t] += add;
        __syncthreads();
    }
    if (t < NBS) g_bsum[t] = sh[t] - v;        // exclusive
}

__global__ void k_scanC() {
    int i = blockIdx.x * blockDim.x + threadIdx.x;
    if (i < Nn) g_eoff[i] += g_bsum[i >> 8];
    if (i == 0) g_eoff[Nn] = Ee;
}

// fused: scatter src into sorted order + compute edge MLP row directly into
// the sorted slot. edge_attr read COALESCED (thread e = edge e).
__global__ void k_scatter_mlp(const int* __restrict__ src, const int* __restrict__ dst,
                              const float* __restrict__ ea,
                              const float* __restrict__ w1, const float* __restrict__ b1) {
    __shared__ float sw1t[16][8];   // [c][f]
    __shared__ float sb1[16];
    if (threadIdx.x < 128) {
        int f = threadIdx.x >> 4, c = threadIdx.x & 15;
        sw1t[c][f] = w1[threadIdx.x];
    }
    if (threadIdx.x < 16) sb1[threadIdx.x] = b1[threadIdx.x];
    __syncthreads();
    int e = blockIdx.x * blockDim.x + threadIdx.x;
    if (e >= Ee) return;
    int d = dst[e];
    int pos = g_eoff[d] + g_rank[e];
    g_srcs[pos] = src[e];
    float4 a0 = *(const float4*)(ea + (size_t)e * 8);
    float4 a1 = *(const float4*)(ea + (size_t)e * 8 + 4);
    float hv[16];
#pragma unroll
    for (int c = 0; c < 16; c++) {
        const float* wc = sw1t[c];
        float acc = sb1[c];
        acc = fmaf(a0.x, wc[0], acc); acc = fmaf(a0.y, wc[1], acc);
        acc = fmaf(a0.z, wc[2], acc); acc = fmaf(a0.w, wc[3], acc);
        acc = fmaf(a1.x, wc[4], acc); acc = fmaf(a1.y, wc[5], acc);
        acc = fmaf(a1.z, wc[6], acc); acc = fmaf(a1.w, wc[7], acc);
        hv[c] = ftanh(acc);
    }
    float4* hp = (float4*)(g_he + (size_t)pos * 16);
    hp[0] = make_float4(hv[0],  hv[1],  hv[2],  hv[3]);
    hp[1] = make_float4(hv[4],  hv[5],  hv[6],  hv[7]);
    hp[2] = make_float4(hv[8],  hv[9],  hv[10], hv[11]);
    hp[3] = make_float4(hv[12], hv[13], hv[14], hv[15]);
}

// ---------------- fused NNConv layer: 2 nodes per warp ----------------
// S[j,i] = sum_e he[e,j]*h[src,i], T[i] = sum_e h[src,i]; contraction against
// transposed+padded w2t[o][row] amortized across the node pair.
__global__ void k_conv(const float* __restrict__ w2g, const float* __restrict__ b2g,
                       const float* __restrict__ rootg, const float* __restrict__ biasg,
                       int layer) {
    __shared__ float sw2t[16 * 264];     // [o][row=j*16+i], pitch 264
    __shared__ float sb2t[16 * 20];      // [o][i], pitch 20
    __shared__ float sroot[256];         // [i*16+o]
    __shared__ float sbias[16];
    __shared__ float sS[8][544];         // per warp: node0 S[256]+T[16], node1 at +272
    __shared__ float bsum[16], bsq[16];

    for (int t = threadIdx.x; t < 4096; t += 256) {
        int row = t >> 4, o = t & 15;
        sw2t[o * 264 + row] = w2g[t];
    }
    if (threadIdx.x < 256) {
        int i = threadIdx.x >> 4, o = threadIdx.x & 15;
        sb2t[o * 20 + i] = b2g[threadIdx.x];
        sroot[threadIdx.x] = rootg[threadIdx.x];
    }
    if (threadIdx.x < 16) { sbias[threadIdx.x] = biasg[threadIdx.x];
                            bsum[threadIdx.x] = 0.f; bsq[threadIdx.x] = 0.f; }
    __syncthreads();

    const unsigned FULL = 0xffffffffu;
    int warp = threadIdx.x >> 5, lane = threadIdx.x & 31;
    int j = lane >> 1;                   // 0..15
    int ibase = (lane & 1) * 8;
    int o = lane & 15;
    int hf = lane >> 4;                  // contraction row-half
    float* ss = sS[warp];
    float lsum = 0.f, lsq = 0.f;

    for (int d0 = blockIdx.x * 16 + warp * 2; d0 < Nn; d0 += gridDim.x * 16) {
        int d1 = d0 + 1;
        // ---- edge loop node 0 ----
        int beg0 = g_eoff[d0], end0 = g_eoff[d0 + 1];
        float A0=0.f,A1=0.f,A2=0.f,A3=0.f,A4=0.f,A5=0.f,A6=0.f,A7=0.f,TA=0.f;
        for (int p = beg0; p < end0; p++) {
            int s = g_srcs[p];
            float a = (lane < 16) ? g_he[(size_t)p * 16 + lane]
                                  : g_h[s * 16 + (lane - 16)];
            float hej = __shfl_sync(FULL, a, j);
            TA += __shfl_sync(FULL, a, 16 + o);
            A0 = fmaf(hej, __shfl_sync(FULL, a, 16 + ibase + 0), A0);
            A1 = fmaf(hej, __shfl_sync(FULL, a, 16 + ibase + 1), A1);
            A2 = fmaf(hej, __shfl_sync(FULL, a, 16 + ibase + 2), A2);
            A3 = fmaf(hej, __shfl_sync(FULL, a, 16 + ibase + 3), A3);
            A4 = fmaf(hej, __shfl_sync(FULL, a, 16 + ibase + 4), A4);
            A5 = fmaf(hej, __shfl_sync(FULL, a, 16 + ibase + 5), A5);
            A6 = fmaf(hej, __shfl_sync(FULL, a, 16 + ibase + 6), A6);
            A7 = fmaf(hej, __shfl_sync(FULL, a, 16 + ibase + 7), A7);
        }
        // ---- edge loop node 1 ----
        float B0=0.f,B1=0.f,B2=0.f,B3=0.f,B4=0.f,B5=0.f,B6=0.f,B7=0.f,TB=0.f;
        int beg1 = 0, end1 = 0;
        if (d1 < Nn) {
            beg1 = g_eoff[d1]; end1 = g_eoff[d1 + 1];
            for (int p = beg1; p < end1; p++) {
                int s = g_srcs[p];
                float a = (lane < 16) ? g_he[(size_t)p * 16 + lane]
                                      : g_h[s * 16 + (lane - 16)];
                float hej = __shfl_sync(FULL, a, j);
                TB += __shfl_sync(FULL, a, 16 + o);
                B0 = fmaf(hej, __shfl_sync(FULL, a, 16 + ibase + 0), B0);
                B1 = fmaf(hej, __shfl_sync(FULL, a, 16 + ibase + 1), B1);
                B2 = fmaf(hej, __shfl_sync(FULL, a, 16 + ibase + 2), B2);
                B3 = fmaf(hej, __shfl_sync(FULL, a, 16 + ibase + 3), B3);
                B4 = fmaf(hej, __shfl_sync(FULL, a, 16 + ibase + 4), B4);
                B5 = fmaf(hej, __shfl_sync(FULL, a, 16 + ibase + 5), B5);
                B6 = fmaf(hej, __shfl_sync(FULL, a, 16 + ibase + 6), B6);
                B7 = fmaf(hej, __shfl_sync(FULL, a, 16 + ibase + 7), B7);
            }
        }
        // ---- stage both nodes' S,T ----
        int sb = j * 16 + ibase;
        *(float4*)&ss[sb]       = make_float4(A0, A1, A2, A3);
        *(float4*)&ss[sb + 4]   = make_float4(A4, A5, A6, A7);
        *(float4*)&ss[272 + sb]     = make_float4(B0, B1, B2, B3);
        *(float4*)&ss[272 + sb + 4] = make_float4(B4, B5, B6, B7);
        if (lane < 16) { ss[256 + lane] = TA; ss[272 + 256 + lane] = TB; }
        __syncwarp();

        // ---- contraction: one pass over w2t serves both nodes ----
        float acc_a = 0.f, acc_b = 0.f;
        const float* wrow = &sw2t[o * 264 + hf * 128];
        const float* sa = &ss[hf * 128];
        const float* sbp = &ss[272 + hf * 128];
#pragma unroll 8
        for (int k = 0; k < 128; k += 4) {
            float4 w  = *(const float4*)(wrow + k);
            float4 xa = *(const float4*)(sa + k);
            float4 xb = *(const float4*)(sbp + k);
            acc_a = fmaf(xa.x, w.x, acc_a); acc_a = fmaf(xa.y, w.y, acc_a);
            acc_a = fmaf(xa.z, w.z, acc_a); acc_a = fmaf(xa.w, w.w, acc_a);
            acc_b = fmaf(xb.x, w.x, acc_b); acc_b = fmaf(xb.y, w.y, acc_b);
            acc_b = fmaf(xb.z, w.z, acc_b); acc_b = fmaf(xb.w, w.w, acc_b);
        }
        {   // b2 @ T terms (i-half per hf)
            const float* brow = &sb2t[o * 20 + hf * 8];
            float4 b0 = *(const float4*)(brow);
            float4 b1 = *(const float4*)(brow + 4);
            float4 t0 = *(const float4*)&ss[256 + hf * 8];
            float4 t1 = *(const float4*)&ss[256 + hf * 8 + 4];
            float4 u0 = *(const float4*)&ss[272 + 256 + hf * 8];
            float4 u1 = *(const float4*)&ss[272 + 256 + hf * 8 + 4];
            acc_a = fmaf(t0.x, b0.x, acc_a); acc_a = fmaf(t0.y, b0.y, acc_a);
            acc_a = fmaf(t0.z, b0.z, acc_a); acc_a = fmaf(t0.w, b0.w, acc_a);
            acc_a = fmaf(t1.x, b1.x, acc_a); acc_a = fmaf(t1.y, b1.y, acc_a);
            acc_a = fmaf(t1.z, b1.z, acc_a); acc_a = fmaf(t1.w, b1.w, acc_a);
            acc_b = fmaf(u0.x, b0.x, acc_b); acc_b = fmaf(u0.y, b0.y, acc_b);
            acc_b = fmaf(u0.z, b0.z, acc_b); acc_b = fmaf(u0.w, b0.w, acc_b);
            acc_b = fmaf(u1.x, b1.x, acc_b); acc_b = fmaf(u1.y, b1.y, acc_b);
            acc_b = fmaf(u1.z, b1.z, acc_b); acc_b = fmaf(u1.w, b1.w, acc_b);
        }
        acc_a += __shfl_down_sync(FULL, acc_a, 16);
        acc_b += __shfl_down_sync(FULL, acc_b, 16);

        // root terms
        float hda = (lane < 16) ? g_h[(size_t)d0 * 16 + lane] : 0.f;
        float hdb = (lane < 16 && d1 < Nn) ? g_h[(size_t)d1 * 16 + lane] : 0.f;
        float ra = 0.f, rb = 0.f;
#pragma unroll
        for (int i = 0; i < 16; i++) {
            float wv = sroot[i * 16 + o];
            ra = fmaf(__shfl_sync(FULL, hda, i), wv, ra);
            rb = fmaf(__shfl_sync(FULL, hdb, i), wv, rb);
        }
        if (lane < 16) {
            float dega = fmaxf((float)(end0 - beg0), 1.0f);
            float resa = acc_a / dega + ra + sbias[o];
            g_h2[(size_t)d0 * 16 + o] = resa;
            lsum += resa; lsq = fmaf(resa, resa, lsq);
            if (d1 < Nn) {
                float degb = fmaxf((float)(end1 - beg1), 1.0f);
                float resb = acc_b / degb + rb + sbias[o];
                g_h2[(size_t)d1 * 16 + o] = resb;
                lsum += resb; lsq = fmaf(resb, resb, lsq);
            }
        }
        __syncwarp();
    }

    if (lane < 16) {
        atomicAdd(&bsum[o], lsum);
        atomicAdd(&bsq[o], lsq);
    }
    __syncthreads();
    if (threadIdx.x < 16) {
        atomicAdd(&g_stat3[layer * 32 + threadIdx.x], (double)bsum[threadIdx.x]);
        atomicAdd(&g_stat3[layer * 32 + 16 + threadIdx.x], (double)bsq[threadIdx.x]);
    }
}

// BN finalize inlined: every thread derives mu/rs from its layer's stat slot.
__global__ void k_apply(const float* __restrict__ gamma,
                        const float* __restrict__ beta,
                        float* __restrict__ hid_out, int layer) {
    int i = blockIdx.x * blockDim.x + threadIdx.x;
    if (i >= Nn * Dd) return;
    int c = i & 15;
    double mu = g_stat3[layer * 32 + c] / (double)Nn;
    double var = g_stat3[layer * 32 + 16 + c] / (double)Nn - mu * mu;
    if (var < 0.0) var = 0.0;
    float rs = rsqrtf((float)var + BN_EPS);
    float v = (g_h2[i] - (float)mu) * rs * __ldg(gamma + c) + __ldg(beta + c);
    v = ftanh(v);
    g_h[i] = v;
    if (hid_out) hid_out[i] = v;
}

// ---------------- fused readout: offsets + pooling + MLP head ----------------
__global__ void k_readout(const int* __restrict__ lengths,
                          const float* __restrict__ fc1w, const float* __restrict__ fc1b,
                          const float* __restrict__ fc2w, const float* __restrict__ fc2b,
                          float* __restrict__ pooled_out,
                          float* __restrict__ fc_out, float* __restrict__ lsm_out) {
    int g = blockIdx.x;
    __shared__ int ired[128];
    __shared__ float rsum[8][17], rmx[8][17], rmn[8][17];
    __shared__ float spool[64];
    __shared__ float sf1[16];
    __shared__ float sfc[10];

    // beg = sum lengths[0..g)
    int part = 0;
    for (int t = threadIdx.x; t < g; t += 128) part += lengths[t];
    ired[threadIdx.x] = part; __syncthreads();
    for (int s = 64; s > 0; s >>= 1) {
        if (threadIdx.x < s) ired[threadIdx.x] += ired[threadIdx.x + s];
        __syncthreads();
    }
    int beg = ired[0];
    int len = lengths[g];
    if (beg > Nn) beg = Nn;
    int end = beg + len; if (end > Nn) end = Nn;

    int c = threadIdx.x & 15, sub = threadIdx.x >> 4;
    float s = 0.f, mx = -INFINITY, mn = INFINITY;
    for (int n = beg + sub; n < end; n += 8) {
        float v = g_h[n * 16 + c];
        s += v; mx = fmaxf(mx, v); mn = fminf(mn, v);
    }
    rsum[sub][c] = s; rmx[sub][c] = mx; rmn[sub][c] = mn;
    __syncthreads();
    if (threadIdx.x < 16) {
        int cc = threadIdx.x;
        float S = 0.f, MX = -INFINITY, MN = INFINITY;
#pragma unroll
        for (int k = 0; k < 8; k++) {
            S += rsum[k][cc];
            MX = fmaxf(MX, rmx[k][cc]);
            MN = fminf(MN, rmn[k][cc]);
        }
        float cnt = fmaxf((float)len, 1.0f);
        spool[cc]      = S / cnt;
        spool[16 + cc] = MX;
        spool[32 + cc] = MN;
        spool[48 + cc] = S;
        pooled_out[g * 64 + cc]      = S / cnt;
        pooled_out[g * 64 + 16 + cc] = MX;
        pooled_out[g * 64 + 32 + cc] = MN;
        pooled_out[g * 64 + 48 + cc] = S;
    }
    __syncthreads();
    if (threadIdx.x < 16) {
        int cc = threadIdx.x;
        float acc = __ldg(fc1b + cc);
#pragma unroll
        for (int i = 0; i < 64; i++)
            acc = fmaf(spool[i], __ldg(fc1w + i * 16 + cc), acc);
        sf1[cc] = ftanh(acc);
    }
    __syncthreads();
    if (threadIdx.x < 10) {
        int cc = threadIdx.x;
        float acc = __ldg(fc2b + cc);
#pragma unroll
        for (int i = 0; i < 16; i++)
            acc = fmaf(sf1[i], __ldg(fc2w + i * 10 + cc), acc);
        sfc[cc] = acc;
        fc_out[g * 10 + cc] = acc;
    }
    __syncthreads();
    if (threadIdx.x < 10) {
        float m = -INFINITY;
#pragma unroll
        for (int k = 0; k < 10; k++) m = fmaxf(m, sfc[k]);
        float sum = 0.f;
#pragma unroll
        for (int k = 0; k < 10; k++) sum += __expf(sfc[k] - m);
        lsm_out[g * 10 + threadIdx.x] = sfc[threadIdx.x] - (m + __logf(sum));
    }
}

// ---------------- launch ----------------
extern "C" void kernel_launch(void* const* d_in, const int* in_sizes, int n_in,
                              void* d_out, int out_size) {
    const float* x         = (const float*)d_in[0];
    const float* edge_attr = (const float*)d_in[1];
    const float* edge_w1   = (const float*)d_in[2];
    const float* edge_b1   = (const float*)d_in[3];
    const float* edge_w2   = (const float*)d_in[4];
    const float* edge_b2   = (const float*)d_in[5];
    const float* root      = (const float*)d_in[6];
    const float* conv_bias = (const float*)d_in[7];
    const float* bn_gamma  = (const float*)d_in[8];
    const float* bn_beta   = (const float*)d_in[9];
    const float* fc1_w     = (const float*)d_in[10];
    const float* fc1_b     = (const float*)d_in[11];
    const float* fc2_w     = (const float*)d_in[12];
    const float* fc2_b     = (const float*)d_in[13];
    const int*   edge_index= (const int*)d_in[14];
    const int*   lengths   = (const int*)d_in[15];
    const int* src = edge_index;
    const int* dst = edge_index + Ee;
    float* out = (float*)d_out;

    // output layout resolution: tuple concat [hidden, pooled, fc, log_softmax]
    const int FULL = Nn * Dd + Gg * 4 * Dd + Gg * Cc + Gg * Cc;  // 842000
    float *hid_dst = nullptr, *pool_dst, *fc_dst, *lsm_dst;
    void *p_pool = nullptr, *p_fc = nullptr;
    cudaGetSymbolAddress(&p_pool, g_pooled);
    cudaGetSymbolAddress(&p_fc, g_fcbuf);
    pool_dst = (float*)p_pool; fc_dst = (float*)p_fc; lsm_dst = (float*)p_fc;
    if (out_size >= FULL) {
        hid_dst  = out;
        pool_dst = out + Nn * Dd;
        fc_dst   = pool_dst + Gg * 4 * Dd;
        lsm_dst  = fc_dst + Gg * Cc;
    } else if (out_size == Gg * Cc) {
        lsm_dst = out;
    } else if (out_size == 2 * Gg * Cc) {
        fc_dst = out; lsm_dst = out + Gg * Cc;
    } else if (out_size == Nn * Dd) {
        hid_dst = out;
    }

    const int B = 256;
    k_setup<<<(Nn * Dd + B - 1) / B, B>>>(x);
    k_hist<<<(Ee + B - 1) / B, B>>>(dst);
    k_scanA<<<NBS, 256>>>();
    k_scanB<<<1, 256>>>();
    k_scanC<<<(Nn + B - 1) / B, B>>>();
    k_scatter_mlp<<<(Ee + 127) / 128, 128>>>(src, dst, edge_attr, edge_w1, edge_b1);

    for (int l = 0; l < 3; l++) {
        k_conv<<<592, 256>>>(edge_w2, edge_b2, root + l * Dd * Dd, conv_bias + l * Dd, l);
        k_apply<<<(Nn * Dd + B - 1) / B, B>>>(bn_gamma + l * Dd, bn_beta + l * Dd,
                                              (l == 2) ? hid_dst : nullptr, l);
    }

    k_readout<<<Gg, 128>>>(lengths, fc1_w, fc1_b, fc2_w, fc2_b,
                           pool_dst, fc_dst, lsm_dst);
}